// round 14
// baseline (speedup 1.0000x reference)
#include <cuda_runtime.h>
#include <cuda_fp16.h>
#include <cstdint>

// Problem dims
#define M_TOTAL 16384   // 8 * 2048
#define N_TOTAL 4096
#define K_TOTAL 4096

// GEMM tiling: 128x128 CTA tile, 2 CTAs resident per SM
#define BM 128
#define BN 128
#define BK 64
#define NK (K_TOTAL / BK)        // 64 mainloop iterations
#define STAGES 3
#define THREADS 320              // 8 consumer warps (2x4, warp tile 64x32) + 2 producer warps

#define A_TILE_BYTES (BM * BK * 2)   // 16384
#define B_TILE_BYTES (BN * BK * 2)   // 16384
#define STAGE_BYTES (A_TILE_BYTES + B_TILE_BYTES)  // 32768
#define SMEM_BIAS   0                // 128 floats
#define SMEM_MBAR   512              // full[3] @512+8s, free[3] @536+8s
#define SMEM_STAGE0 1024
#define SMEM_TOTAL  (SMEM_STAGE0 + STAGES * STAGE_BYTES)  // 99328 (x2 CTAs <= 227KB)

// fp16 operand buffers (device globals: no runtime allocation allowed)
__device__ __align__(1024) __half g_xh[(size_t)M_TOTAL * K_TOTAL];
__device__ __align__(1024) __half g_wh[(size_t)N_TOTAL * K_TOTAL];

// ---------------------------------------------------------------- helpers

__device__ __forceinline__ uint32_t smem_u32(const void* p) {
    uint32_t a;
    asm("{ .reg .u64 t; cvta.to.shared.u64 t, %1; cvt.u32.u64 %0, t; }" : "=r"(a) : "l"(p));
    return a;
}

__device__ __forceinline__ uint32_t swz128(uint32_t off) {
    return off ^ ((off >> 3) & 0x70);
}

__device__ __forceinline__ float quantize_ste(float w) {
    float a = fminf(fabsf(w), 1.0f);
    float q = rintf(a * 255.0f) * (1.0f / 255.0f);
    return copysignf(q, w);
}

__device__ __forceinline__ uint32_t h2_as_u32(__half2 h) {
    return *reinterpret_cast<uint32_t*>(&h);
}

__device__ __forceinline__ void cp_async16(uint32_t dst, const void* src) {
    asm volatile("cp.async.cg.shared.global [%0], [%1], 16;" :: "r"(dst), "l"(src) : "memory");
}
__device__ __forceinline__ void cp_async_arrive(uint32_t mbar) {
    asm volatile("cp.async.mbarrier.arrive.noinc.shared.b64 [%0];" :: "r"(mbar) : "memory");
}

#define MBAR_INIT(a, n) \
    asm volatile("mbarrier.init.shared.b64 [%0], %1;" :: "r"(a), "r"((uint32_t)(n)) : "memory")
#define MBAR_ARRIVE(a) \
    asm volatile("mbarrier.arrive.shared.b64 _, [%0];" :: "r"(a) : "memory")

__device__ __forceinline__ void mbar_wait(uint32_t mbar, uint32_t parity) {
    uint32_t done;
    asm volatile(
        "{\n\t.reg .pred p;\n\t"
        "mbarrier.try_wait.parity.acquire.cta.shared::cta.b64 p, [%1], %2;\n\t"
        "selp.b32 %0, 1, 0, p;\n\t}"
        : "=r"(done) : "r"(mbar), "r"(parity) : "memory");
    if (!done) {
        asm volatile(
            "{\n\t.reg .pred P1;\n\t"
            "WL_%=:\n\t"
            "mbarrier.try_wait.parity.acquire.cta.shared::cta.b64 P1, [%0], %1, 0x989680;\n\t"
            "@P1 bra.uni WD_%=;\n\t"
            "bra.uni WL_%=;\n\t"
            "WD_%=:\n\t}"
            :: "r"(mbar), "r"(parity) : "memory");
    }
}

__device__ __forceinline__ void ldsm_x4(uint32_t* r, uint32_t addr) {
    asm volatile("ldmatrix.sync.aligned.m8n8.x4.shared.b16 {%0,%1,%2,%3}, [%4];"
                 : "=r"(r[0]), "=r"(r[1]), "=r"(r[2]), "=r"(r[3]) : "r"(addr));
}

__device__ __forceinline__ void mma_16816(float* c, const uint32_t* a, uint32_t b0, uint32_t b1) {
    asm volatile(
        "mma.sync.aligned.m16n8k16.row.col.f32.f16.f16.f32 "
        "{%0,%1,%2,%3}, {%4,%5,%6,%7}, {%8,%9}, {%0,%1,%2,%3};"
        : "+f"(c[0]), "+f"(c[1]), "+f"(c[2]), "+f"(c[3])
        : "r"(a[0]), "r"(a[1]), "r"(a[2]), "r"(a[3]), "r"(b0), "r"(b1));
}

// ---------------------------------------------------------------- pre-pass kernels

__global__ void convert_x_kernel(const float* __restrict__ x) {
    size_t e = ((size_t)blockIdx.x * blockDim.x + threadIdx.x) * 8;
    float4 a = *reinterpret_cast<const float4*>(x + e);
    float4 b = *reinterpret_cast<const float4*>(x + e + 4);
    uint4 o;
    o.x = h2_as_u32(__floats2half2_rn(a.x, a.y));
    o.y = h2_as_u32(__floats2half2_rn(a.z, a.w));
    o.z = h2_as_u32(__floats2half2_rn(b.x, b.y));
    o.w = h2_as_u32(__floats2half2_rn(b.z, b.w));
    *reinterpret_cast<uint4*>(g_xh + e) = o;
}

__global__ void convert_w_kernel(const float* __restrict__ w) {
    size_t e = ((size_t)blockIdx.x * blockDim.x + threadIdx.x) * 8;
    float4 a = *reinterpret_cast<const float4*>(w + e);
    float4 b = *reinterpret_cast<const float4*>(w + e + 4);
    uint4 o;
    o.x = h2_as_u32(__floats2half2_rn(quantize_ste(a.x), quantize_ste(a.y)));
    o.y = h2_as_u32(__floats2half2_rn(quantize_ste(a.z), quantize_ste(a.w)));
    o.z = h2_as_u32(__floats2half2_rn(quantize_ste(b.x), quantize_ste(b.y)));
    o.w = h2_as_u32(__floats2half2_rn(quantize_ste(b.z), quantize_ste(b.w)));
    *reinterpret_cast<uint4*>(g_wh + e) = o;
}

// no-op: shifts launch index so ncu (-s 5 -c 1) lands on the GEMM
__global__ void align_nop_kernel() {}

// ---------------------------------------------------------------- GEMM kernel
// Warp-specialized: warps 0-7 = consumers (2x4 grid, warp tile 64x32),
// warps 8-9 = producers (all cp.async). 2 CTAs/SM.
// full[s]: count 64 (producer threads, cp.async.arrive.noinc)
// free[s]: count 8  (consumer warps, lane-0 arrive after last ldmatrix)
//
// Swizzle hoisting: for a base offset with bits [5:6] == 0 and koff in bits
// [5:6], swz128(base + koff) == swz128(base) ^ koff  (XOR, NOT add — the add
// form carries into bit 7 and overflows the last stage: the R13 crash).

__global__ void __launch_bounds__(THREADS, 2)
bitlinear_gemm(const float* __restrict__ bias, float* __restrict__ out) {
    extern __shared__ char smem[];
    uint32_t sb = smem_u32(smem);
    const int tid = threadIdx.x;
    const int wid = tid >> 5, lane = tid & 31;
    const uint32_t mt = blockIdx.y, nt = blockIdx.x;

    float* qb = reinterpret_cast<float*>(smem + SMEM_BIAS);
    if (tid < BN) qb[tid] = quantize_ste(bias[nt * BN + tid]);

    if (tid == 0) {
        #pragma unroll
        for (int s = 0; s < STAGES; s++) {
            MBAR_INIT(sb + SMEM_MBAR + s * 8, 64);            // full[s]: 64 producer threads
            MBAR_INIT(sb + SMEM_MBAR + 24 + s * 8, 8);        // free[s]: 8 consumer warps
        }
    }
    __syncthreads();

    if (wid >= 8) {
        // ================= PRODUCER (warps 8,9; 64 threads) =================
        const int ptid = tid - 256;                 // 0..63
        const int prow = ptid >> 3, pkc = ptid & 7; // rows prow+8i, fixed 16B column pkc
        const __half* aptr = g_xh + (size_t)mt * BM * K_TOTAL + (size_t)prow * K_TOTAL + pkc * 8;
        const __half* bptr = g_wh + (size_t)nt * BN * K_TOTAL + (size_t)prow * K_TOTAL + pkc * 8;
        // swz128(off + i*1024) = swz128(off) + i*1024 (i*1024 only sets bits >= 10)
        const uint32_t adst0 = sb + SMEM_STAGE0 + swz128(prow * 128 + pkc * 16);
        const uint32_t bdst0 = adst0 + A_TILE_BYTES;

        int psd = 0, pfw = 0;
        for (int kt = 0; kt < NK; kt++) {
            if (kt >= STAGES) {
                mbar_wait(sb + SMEM_MBAR + 24 + psd * 8, pfw);
                if (psd == STAGES - 1) pfw ^= 1;
            }
            uint32_t as = adst0 + psd * STAGE_BYTES;
            uint32_t bs = bdst0 + psd * STAGE_BYTES;
            #pragma unroll
            for (int i = 0; i < 16; i++)           // 16 A chunks: rows prow+8i
                cp_async16(as + i * 1024, aptr + (size_t)i * 8 * K_TOTAL);
            #pragma unroll
            for (int i = 0; i < 16; i++)           // 16 B chunks
                cp_async16(bs + i * 1024, bptr + (size_t)i * 8 * K_TOTAL);
            cp_async_arrive(sb + SMEM_MBAR + psd * 8);
            aptr += BK;
            bptr += BK;
            if (++psd == STAGES) psd = 0;
        }
        return;
    }

    // ================= CONSUMER (warps 0-7) =================
    const int warp_m = wid >> 2, warp_n = wid & 3;          // 2 x 4 grid
    const int lrow = (lane & 7) + ((lane >> 3) & 1) * 8;
    const int lhi = lane >> 4;

    // hoisted swizzled fragment offsets (relative to stage base).
    // Base bits [5:6] are zero (row*128 has bits >=7, lhi*16 is bit 4), so
    // per-kk advance is XOR with koff = kk*32 (bits [5:6]).
    uint32_t off_a[4], off_b[2];
    #pragma unroll
    for (int mi = 0; mi < 4; mi++)
        off_a[mi] = swz128((warp_m * 64 + mi * 16 + lrow) * 128 + lhi * 16);
    #pragma unroll
    for (int ni = 0; ni < 2; ni++)
        off_b[ni] = swz128((warp_n * 32 + ni * 16 + lrow) * 128 + lhi * 16);

    float acc[4][4][4];
    #pragma unroll
    for (int i = 0; i < 4; i++)
        #pragma unroll
        for (int j = 0; j < 4; j++)
            #pragma unroll
            for (int c = 0; c < 4; c++) acc[i][j][c] = 0.0f;

    int cons_s = 0, cons_ph = 0;
    for (int kt = 0; kt < NK; kt++) {
        mbar_wait(sb + SMEM_MBAR + cons_s * 8, cons_ph);
        uint32_t abase = sb + SMEM_STAGE0 + cons_s * STAGE_BYTES;
        uint32_t bbase = abase + A_TILE_BYTES;

        #pragma unroll
        for (int kk = 0; kk < 4; kk++) {
            uint32_t koff = kk * 32;
            uint32_t b[2][4];
            ldsm_x4(b[0], bbase + (off_b[0] ^ koff));
            ldsm_x4(b[1], bbase + (off_b[1] ^ koff));
            uint32_t a[2][4];
            ldsm_x4(a[0], abase + (off_a[0] ^ koff));
            #pragma unroll
            for (int mi = 0; mi < 4; mi++) {
                int cur = mi & 1;
                if (mi < 3) ldsm_x4(a[cur ^ 1], abase + (off_a[mi + 1] ^ koff));
                // after the mi==2 prefetch (a[3]) this warp has issued every
                // ldmatrix touching this stage -> release it to the producer
                if (kk == 3 && mi == 2 && lane == 0)
                    MBAR_ARRIVE(sb + SMEM_MBAR + 24 + cons_s * 8);
                #pragma unroll
                for (int j = 0; j < 4; j++) {
                    int ni = j >> 1, sel = j & 1;
                    mma_16816(acc[mi][j], a[cur], b[ni][0 + sel], b[ni][2 + sel]);
                }
            }
        }
        if (++cons_s == STAGES) { cons_s = 0; cons_ph ^= 1; }
    }

    // ---- epilogue: registers -> gmem with quantized bias ----
    const int qrow = lane >> 2, qcol = (lane & 3) * 2;
    #pragma unroll
    for (int mi = 0; mi < 4; mi++) {
        #pragma unroll
        for (int j = 0; j < 4; j++) {
            int n_off = warp_n * 32 + j * 8 + qcol;
            float b0 = qb[n_off], b1 = qb[n_off + 1];
            size_t m0 = (size_t)mt * BM + warp_m * 64 + mi * 16 + qrow;
            float* p0 = out + m0 * N_TOTAL + nt * BN + n_off;
            float* p1 = p0 + 8 * N_TOTAL;
            float2 v0 = {acc[mi][j][0] + b0, acc[mi][j][1] + b1};
            float2 v1 = {acc[mi][j][2] + b0, acc[mi][j][3] + b1};
            *reinterpret_cast<float2*>(p0) = v0;
            *reinterpret_cast<float2*>(p1) = v1;
        }
    }
}

// ---------------------------------------------------------------- launch

extern "C" void kernel_launch(void* const* d_in, const int* in_sizes, int n_in,
                              void* d_out, int out_size) {
    const float* x = (const float*)d_in[0];       // [8, 2048, 4096]
    const float* w = (const float*)d_in[1];       // [4096, 4096]
    const float* b = (const float*)d_in[2];       // [4096]
    float* out = (float*)d_out;

    cudaFuncSetAttribute(bitlinear_gemm,
                         cudaFuncAttributeMaxDynamicSharedMemorySize, SMEM_TOTAL);

    convert_x_kernel<<<32768, 256>>>(x);          // 64M halfs / 8 per thread
    convert_w_kernel<<<8192, 256>>>(w);           // 16M halfs / 8 per thread
    align_nop_kernel<<<1, 32>>>();                // shift ncu -s 5 onto the GEMM
    bitlinear_gemm<<<dim3(N_TOTAL / BN, M_TOTAL / BM), THREADS, SMEM_TOTAL>>>(b, out);
}

// round 15
// speedup vs baseline: 1.0252x; 1.0252x over previous
#include <cuda_runtime.h>
#include <cuda_fp16.h>
#include <cstdint>

// Problem dims
#define M_TOTAL 16384   // 8 * 2048
#define N_TOTAL 4096
#define K_TOTAL 4096

// GEMM tiling: 128x128 CTA tile, 2 CTAs resident per SM
#define BM 128
#define BN 128
#define BK 64
#define NK (K_TOTAL / BK)        // 64 mainloop iterations
#define STAGES 3
#define THREADS 128              // 4 warps; 2x2 warp grid; warp tile 64x64

#define A_TILE_BYTES (BM * BK * 2)   // 16384
#define B_TILE_BYTES (BN * BK * 2)   // 16384
#define STAGE_BYTES (A_TILE_BYTES + B_TILE_BYTES)  // 32768
#define SMEM_BIAS   0                // 128 floats
#define SMEM_MBAR   512              // full[3] @512+8s, free[3] @536+8s
#define SMEM_STAGE0 1024
#define SMEM_TOTAL  (SMEM_STAGE0 + STAGES * STAGE_BYTES)  // 99328 (x2 CTAs <= 227KB)

// fp16 operand buffers (device globals: no runtime allocation allowed)
__device__ __align__(1024) __half g_xh[(size_t)M_TOTAL * K_TOTAL];
__device__ __align__(1024) __half g_wh[(size_t)N_TOTAL * K_TOTAL];

// ---------------------------------------------------------------- helpers

__device__ __forceinline__ uint32_t smem_u32(const void* p) {
    uint32_t a;
    asm("{ .reg .u64 t; cvta.to.shared.u64 t, %1; cvt.u32.u64 %0, t; }" : "=r"(a) : "l"(p));
    return a;
}

__device__ __forceinline__ uint32_t swz128(uint32_t off) {
    return off ^ ((off >> 3) & 0x70);
}

__device__ __forceinline__ float quantize_ste(float w) {
    float a = fminf(fabsf(w), 1.0f);
    float q = rintf(a * 255.0f) * (1.0f / 255.0f);
    return copysignf(q, w);
}

__device__ __forceinline__ uint32_t h2_as_u32(__half2 h) {
    return *reinterpret_cast<uint32_t*>(&h);
}

__device__ __forceinline__ void cp_async16(uint32_t dst, const void* src) {
    asm volatile("cp.async.cg.shared.global [%0], [%1], 16;" :: "r"(dst), "l"(src) : "memory");
}
__device__ __forceinline__ void cp_async_arrive(uint32_t mbar) {
    asm volatile("cp.async.mbarrier.arrive.noinc.shared.b64 [%0];" :: "r"(mbar) : "memory");
}

#define MBAR_INIT(a, n) \
    asm volatile("mbarrier.init.shared.b64 [%0], %1;" :: "r"(a), "r"((uint32_t)(n)) : "memory")
#define MBAR_ARRIVE(a) \
    asm volatile("mbarrier.arrive.shared.b64 _, [%0];" :: "r"(a) : "memory")

__device__ __forceinline__ void mbar_wait(uint32_t mbar, uint32_t parity) {
    uint32_t done;
    asm volatile(
        "{\n\t.reg .pred p;\n\t"
        "mbarrier.try_wait.parity.acquire.cta.shared::cta.b64 p, [%1], %2;\n\t"
        "selp.b32 %0, 1, 0, p;\n\t}"
        : "=r"(done) : "r"(mbar), "r"(parity) : "memory");
    if (!done) {
        asm volatile(
            "{\n\t.reg .pred P1;\n\t"
            "WL_%=:\n\t"
            "mbarrier.try_wait.parity.acquire.cta.shared::cta.b64 P1, [%0], %1, 0x989680;\n\t"
            "@P1 bra.uni WD_%=;\n\t"
            "bra.uni WL_%=;\n\t"
            "WD_%=:\n\t}"
            :: "r"(mbar), "r"(parity) : "memory");
    }
}

__device__ __forceinline__ void ldsm_x4(uint32_t* r, uint32_t addr) {
    asm volatile("ldmatrix.sync.aligned.m8n8.x4.shared.b16 {%0,%1,%2,%3}, [%4];"
                 : "=r"(r[0]), "=r"(r[1]), "=r"(r[2]), "=r"(r[3]) : "r"(addr));
}

__device__ __forceinline__ void mma_16816(float* c, const uint32_t* a, uint32_t b0, uint32_t b1) {
    asm volatile(
        "mma.sync.aligned.m16n8k16.row.col.f32.f16.f16.f32 "
        "{%0,%1,%2,%3}, {%4,%5,%6,%7}, {%8,%9}, {%0,%1,%2,%3};"
        : "+f"(c[0]), "+f"(c[1]), "+f"(c[2]), "+f"(c[3])
        : "r"(a[0]), "r"(a[1]), "r"(a[2]), "r"(a[3]), "r"(b0), "r"(b1));
}

// ---------------------------------------------------------------- pre-pass kernels

__global__ void convert_x_kernel(const float* __restrict__ x) {
    size_t e = ((size_t)blockIdx.x * blockDim.x + threadIdx.x) * 8;
    float4 a = *reinterpret_cast<const float4*>(x + e);
    float4 b = *reinterpret_cast<const float4*>(x + e + 4);
    uint4 o;
    o.x = h2_as_u32(__floats2half2_rn(a.x, a.y));
    o.y = h2_as_u32(__floats2half2_rn(a.z, a.w));
    o.z = h2_as_u32(__floats2half2_rn(b.x, b.y));
    o.w = h2_as_u32(__floats2half2_rn(b.z, b.w));
    *reinterpret_cast<uint4*>(g_xh + e) = o;
}

__global__ void convert_w_kernel(const float* __restrict__ w) {
    size_t e = ((size_t)blockIdx.x * blockDim.x + threadIdx.x) * 8;
    float4 a = *reinterpret_cast<const float4*>(w + e);
    float4 b = *reinterpret_cast<const float4*>(w + e + 4);
    uint4 o;
    o.x = h2_as_u32(__floats2half2_rn(quantize_ste(a.x), quantize_ste(a.y)));
    o.y = h2_as_u32(__floats2half2_rn(quantize_ste(a.z), quantize_ste(a.w)));
    o.z = h2_as_u32(__floats2half2_rn(quantize_ste(b.x), quantize_ste(b.y)));
    o.w = h2_as_u32(__floats2half2_rn(quantize_ste(b.z), quantize_ste(b.w)));
    *reinterpret_cast<uint4*>(g_wh + e) = o;
}

// no-op: shifts launch index so ncu (-s 5 -c 1) lands on the GEMM
__global__ void align_nop_kernel() {}

// ---------------------------------------------------------------- GEMM kernel
// CTA 128x128, BK=64, 128 threads, 4 warps (2 x 2), warp tile 64x64, 2 CTAs/SM.
// R12 skeleton (embedded producer, per-stage mbarriers, strength-reduced
// pointers, early release). Wider warp tile cuts LDSM traffic per MMA by 33%
// (0.375 -> 0.25 ldsm.x4 per mma), dropping crossbar demand below tensor demand.
// full[s]: count 128 (all threads cp.async.arrive.noinc)
// free[s]: count 4   (consumer warps, lane-0 arrive after last ldmatrix)

__global__ void __launch_bounds__(THREADS, 2)
bitlinear_gemm(const float* __restrict__ bias, float* __restrict__ out) {
    extern __shared__ char smem[];
    uint32_t sb = smem_u32(smem);
    const int tid = threadIdx.x;
    const int wid = tid >> 5, lane = tid & 31;
    const int warp_m = wid >> 1, warp_n = wid & 1;     // 2 x 2 warps
    const uint32_t mt = blockIdx.y, nt = blockIdx.x;

    float* qb = reinterpret_cast<float*>(smem + SMEM_BIAS);
    if (tid < BN) qb[tid] = quantize_ste(bias[nt * BN + tid]);

    if (tid == 0) {
        #pragma unroll
        for (int s = 0; s < STAGES; s++) {
            MBAR_INIT(sb + SMEM_MBAR + s * 8, THREADS);       // full[s]
            MBAR_INIT(sb + SMEM_MBAR + 24 + s * 8, 4);        // free[s]
        }
    }
    __syncthreads();

    // ---- strength-reduced producer state ----
    // chunk i (i<8): c = tid + i*128 -> row = (tid>>3) + 16i, kc = tid&7
    // gmem step per i = 16*K_TOTAL halfs; smem step per i = 2048 B (swz-invariant)
    const int trow = tid >> 3, tkc = tid & 7;
    const __half* aptr = g_xh + (size_t)mt * BM * K_TOTAL + (size_t)trow * K_TOTAL + tkc * 8;
    const __half* bptr = g_wh + (size_t)nt * BN * K_TOTAL + (size_t)trow * K_TOTAL + tkc * 8;
    const uint32_t adst0 = sb + SMEM_STAGE0 + swz128(trow * 128 + tkc * 16);
    const uint32_t bdst0 = adst0 + A_TILE_BYTES;

    int psd = 0;
    auto produce = [&]() {
        uint32_t as = adst0 + psd * STAGE_BYTES;
        uint32_t bs = bdst0 + psd * STAGE_BYTES;
        #pragma unroll
        for (int i = 0; i < 8; i++)
            cp_async16(as + i * 2048, aptr + (size_t)i * 16 * K_TOTAL);
        #pragma unroll
        for (int i = 0; i < 8; i++)
            cp_async16(bs + i * 2048, bptr + (size_t)i * 16 * K_TOTAL);
        cp_async_arrive(sb + SMEM_MBAR + psd * 8);
        aptr += BK;
        bptr += BK;
        if (++psd == STAGES) psd = 0;
    };

    produce();   // kt = 0 -> stage 0
    produce();   // kt = 1 -> stage 1

    // per-lane ldmatrix row mapping
    const int lrow = (lane & 7) + ((lane >> 3) & 1) * 8;
    const int lhi = lane >> 4;

    float acc[4][8][4];
    #pragma unroll
    for (int i = 0; i < 4; i++)
        #pragma unroll
        for (int j = 0; j < 8; j++)
            #pragma unroll
            for (int c = 0; c < 4; c++) acc[i][j][c] = 0.0f;

    int cons_s = 0, cons_ph = 0;
    int prod_fw = 0;                             // first free-wait on each stage: parity 0

    for (int kt = 0; kt < NK; kt++) {
        if (kt + 2 < NK) {
            if (kt > 0) {
                mbar_wait(sb + SMEM_MBAR + 24 + psd * 8, prod_fw);
                if (psd == STAGES - 1) prod_fw ^= 1;
            }
            produce();
        }

        mbar_wait(sb + SMEM_MBAR + cons_s * 8, cons_ph);
        uint32_t abase = sb + SMEM_STAGE0 + cons_s * STAGE_BYTES;
        uint32_t bbase = abase + A_TILE_BYTES;

        #pragma unroll
        for (int kk = 0; kk < 4; kk++) {
            uint32_t kc = (kk * 2 + lhi) * 16;
            uint32_t b[4][4];
            #pragma unroll
            for (int ni = 0; ni < 4; ni++) {
                int row = warp_n * 64 + ni * 16 + lrow;
                ldsm_x4(b[ni], bbase + swz128(row * 128 + kc));
            }
            uint32_t a[2][4];
            ldsm_x4(a[0], abase + swz128((warp_m * 64 + lrow) * 128 + kc));
            #pragma unroll
            for (int mi = 0; mi < 4; mi++) {
                int cur = mi & 1;
                if (mi < 3) {
                    int row = warp_m * 64 + (mi + 1) * 16 + lrow;
                    ldsm_x4(a[cur ^ 1], abase + swz128(row * 128 + kc));
                }
                // after the mi==2 prefetch (a[3]) all ldmatrix for this stage issued
                if (kk == 3 && mi == 2 && lane == 0)
                    MBAR_ARRIVE(sb + SMEM_MBAR + 24 + cons_s * 8);
                #pragma unroll
                for (int j = 0; j < 8; j++) {
                    int ni = j >> 1, sel = j & 1;
                    mma_16816(acc[mi][j], a[cur], b[ni][0 + sel], b[ni][2 + sel]);
                }
            }
        }
        if (++cons_s == STAGES) { cons_s = 0; cons_ph ^= 1; }
    }

    // ---- epilogue: registers -> gmem with quantized bias ----
    const int qrow = lane >> 2, qcol = (lane & 3) * 2;
    #pragma unroll
    for (int mi = 0; mi < 4; mi++) {
        #pragma unroll
        for (int j = 0; j < 8; j++) {
            int n_off = warp_n * 64 + j * 8 + qcol;
            float b0 = qb[n_off], b1 = qb[n_off + 1];
            size_t m0 = (size_t)mt * BM + warp_m * 64 + mi * 16 + qrow;
            float* p0 = out + m0 * N_TOTAL + nt * BN + n_off;
            float* p1 = p0 + 8 * N_TOTAL;
            float2 v0 = {acc[mi][j][0] + b0, acc[mi][j][1] + b1};
            float2 v1 = {acc[mi][j][2] + b0, acc[mi][j][3] + b1};
            *reinterpret_cast<float2*>(p0) = v0;
            *reinterpret_cast<float2*>(p1) = v1;
        }
    }
}

// ---------------------------------------------------------------- launch

extern "C" void kernel_launch(void* const* d_in, const int* in_sizes, int n_in,
                              void* d_out, int out_size) {
    const float* x = (const float*)d_in[0];       // [8, 2048, 4096]
    const float* w = (const float*)d_in[1];       // [4096, 4096]
    const float* b = (const float*)d_in[2];       // [4096]
    float* out = (float*)d_out;

    cudaFuncSetAttribute(bitlinear_gemm,
                         cudaFuncAttributeMaxDynamicSharedMemorySize, SMEM_TOTAL);

    convert_x_kernel<<<32768, 256>>>(x);          // 64M halfs / 8 per thread
    convert_w_kernel<<<8192, 256>>>(w);           // 16M halfs / 8 per thread
    align_nop_kernel<<<1, 32>>>();                // shift ncu -s 5 onto the GEMM
    bitlinear_gemm<<<dim3(N_TOTAL / BN, M_TOTAL / BM), THREADS, SMEM_TOTAL>>>(b, out);
}

// round 16
// speedup vs baseline: 1.0327x; 1.0073x over previous
#include <cuda_runtime.h>
#include <cuda_fp16.h>
#include <cstdint>

// Problem dims
#define M_TOTAL 16384   // 8 * 2048
#define N_TOTAL 4096
#define K_TOTAL 4096

// GEMM tiling: 128x128 CTA tile, 2 CTAs resident per SM
#define BM 128
#define BN 128
#define BK 64
#define NK (K_TOTAL / BK)        // 64 mainloop iterations
#define STAGES 3
#define THREADS 128              // 4 warps; 2x2 warp grid; warp tile 64x64

#define A_TILE_BYTES (BM * BK * 2)   // 16384
#define B_TILE_BYTES (BN * BK * 2)   // 16384
#define STAGE_BYTES (A_TILE_BYTES + B_TILE_BYTES)  // 32768
#define SMEM_BIAS   0                // 128 floats
#define SMEM_MBAR   512              // full[3] @512+8s, free[3] @536+8s
#define SMEM_STAGE0 1024
#define SMEM_TOTAL  (SMEM_STAGE0 + STAGES * STAGE_BYTES)  // 99328 (x2 CTAs <= 227KB)

// fp16 operand buffers (device globals: no runtime allocation allowed)
__device__ __align__(1024) __half g_xh[(size_t)M_TOTAL * K_TOTAL];
__device__ __align__(1024) __half g_wh[(size_t)N_TOTAL * K_TOTAL];

// ---------------------------------------------------------------- helpers

__device__ __forceinline__ uint32_t smem_u32(const void* p) {
    uint32_t a;
    asm("{ .reg .u64 t; cvta.to.shared.u64 t, %1; cvt.u32.u64 %0, t; }" : "=r"(a) : "l"(p));
    return a;
}

__device__ __forceinline__ uint32_t swz128(uint32_t off) {
    return off ^ ((off >> 3) & 0x70);
}

__device__ __forceinline__ float quantize_ste(float w) {
    float a = fminf(fabsf(w), 1.0f);
    float q = rintf(a * 255.0f) * (1.0f / 255.0f);
    return copysignf(q, w);
}

__device__ __forceinline__ uint32_t h2_as_u32(__half2 h) {
    return *reinterpret_cast<uint32_t*>(&h);
}

__device__ __forceinline__ void cp_async16(uint32_t dst, const void* src) {
    asm volatile("cp.async.cg.shared.global [%0], [%1], 16;" :: "r"(dst), "l"(src) : "memory");
}
__device__ __forceinline__ void cp_async_arrive(uint32_t mbar) {
    asm volatile("cp.async.mbarrier.arrive.noinc.shared.b64 [%0];" :: "r"(mbar) : "memory");
}

#define MBAR_INIT(a, n) \
    asm volatile("mbarrier.init.shared.b64 [%0], %1;" :: "r"(a), "r"((uint32_t)(n)) : "memory")
#define MBAR_ARRIVE(a) \
    asm volatile("mbarrier.arrive.shared.b64 _, [%0];" :: "r"(a) : "memory")

__device__ __forceinline__ void mbar_wait(uint32_t mbar, uint32_t parity) {
    uint32_t done;
    asm volatile(
        "{\n\t.reg .pred p;\n\t"
        "mbarrier.try_wait.parity.acquire.cta.shared::cta.b64 p, [%1], %2;\n\t"
        "selp.b32 %0, 1, 0, p;\n\t}"
        : "=r"(done) : "r"(mbar), "r"(parity) : "memory");
    if (!done) {
        asm volatile(
            "{\n\t.reg .pred P1;\n\t"
            "WL_%=:\n\t"
            "mbarrier.try_wait.parity.acquire.cta.shared::cta.b64 P1, [%0], %1, 0x989680;\n\t"
            "@P1 bra.uni WD_%=;\n\t"
            "bra.uni WL_%=;\n\t"
            "WD_%=:\n\t}"
            :: "r"(mbar), "r"(parity) : "memory");
    }
}

__device__ __forceinline__ void ldsm_x4(uint32_t* r, uint32_t addr) {
    asm volatile("ldmatrix.sync.aligned.m8n8.x4.shared.b16 {%0,%1,%2,%3}, [%4];"
                 : "=r"(r[0]), "=r"(r[1]), "=r"(r[2]), "=r"(r[3]) : "r"(addr));
}

__device__ __forceinline__ void mma_16816(float* c, const uint32_t* a, uint32_t b0, uint32_t b1) {
    asm volatile(
        "mma.sync.aligned.m16n8k16.row.col.f32.f16.f16.f32 "
        "{%0,%1,%2,%3}, {%4,%5,%6,%7}, {%8,%9}, {%0,%1,%2,%3};"
        : "+f"(c[0]), "+f"(c[1]), "+f"(c[2]), "+f"(c[3])
        : "r"(a[0]), "r"(a[1]), "r"(a[2]), "r"(a[3]), "r"(b0), "r"(b1));
}

// ---------------------------------------------------------------- pre-pass kernels

__global__ void convert_x_kernel(const float* __restrict__ x) {
    size_t e = ((size_t)blockIdx.x * blockDim.x + threadIdx.x) * 8;
    float4 a = *reinterpret_cast<const float4*>(x + e);
    float4 b = *reinterpret_cast<const float4*>(x + e + 4);
    uint4 o;
    o.x = h2_as_u32(__floats2half2_rn(a.x, a.y));
    o.y = h2_as_u32(__floats2half2_rn(a.z, a.w));
    o.z = h2_as_u32(__floats2half2_rn(b.x, b.y));
    o.w = h2_as_u32(__floats2half2_rn(b.z, b.w));
    *reinterpret_cast<uint4*>(g_xh + e) = o;
}

__global__ void convert_w_kernel(const float* __restrict__ w) {
    size_t e = ((size_t)blockIdx.x * blockDim.x + threadIdx.x) * 8;
    float4 a = *reinterpret_cast<const float4*>(w + e);
    float4 b = *reinterpret_cast<const float4*>(w + e + 4);
    uint4 o;
    o.x = h2_as_u32(__floats2half2_rn(quantize_ste(a.x), quantize_ste(a.y)));
    o.y = h2_as_u32(__floats2half2_rn(quantize_ste(a.z), quantize_ste(a.w)));
    o.z = h2_as_u32(__floats2half2_rn(quantize_ste(b.x), quantize_ste(b.y)));
    o.w = h2_as_u32(__floats2half2_rn(quantize_ste(b.z), quantize_ste(b.w)));
    *reinterpret_cast<uint4*>(g_wh + e) = o;
}

// no-op: shifts launch index so ncu (-s 5 -c 1) lands on the GEMM
__global__ void align_nop_kernel() {}

// ---------------------------------------------------------------- GEMM kernel
// CTA 128x128, BK=64, 128 threads, 4 warps (2 x 2), warp tile 64x64, 2 CTAs/SM.
// R15 skeleton + two critical-path cuts:
//  (1) hoisted XOR fragment addressing: off = swz128(row*128 + lhi*16) computed
//      once; per-kk address = base + (off ^ kk*32). Valid since pre-swizzle
//      bits [5:6] of the base are 0 -> composition is pure XOR (R14-proven).
//  (2) cross-kk double-buffered fragments (af/bf[2]): kk+1's 8 ldsm issue
//      inside kk's 32-MMA window, hiding LDS latency (reg budget: 255/thread
//      at 2 CTAs x 128 thr; est ~225 used).

__global__ void __launch_bounds__(THREADS, 2)
bitlinear_gemm(const float* __restrict__ bias, float* __restrict__ out) {
    extern __shared__ char smem[];
    uint32_t sb = smem_u32(smem);
    const int tid = threadIdx.x;
    const int wid = tid >> 5, lane = tid & 31;
    const int warp_m = wid >> 1, warp_n = wid & 1;     // 2 x 2 warps
    const uint32_t mt = blockIdx.y, nt = blockIdx.x;

    float* qb = reinterpret_cast<float*>(smem + SMEM_BIAS);
    if (tid < BN) qb[tid] = quantize_ste(bias[nt * BN + tid]);

    if (tid == 0) {
        #pragma unroll
        for (int s = 0; s < STAGES; s++) {
            MBAR_INIT(sb + SMEM_MBAR + s * 8, THREADS);       // full[s]
            MBAR_INIT(sb + SMEM_MBAR + 24 + s * 8, 4);        // free[s]
        }
    }
    __syncthreads();

    // ---- strength-reduced producer state ----
    const int trow = tid >> 3, tkc = tid & 7;
    const __half* aptr = g_xh + (size_t)mt * BM * K_TOTAL + (size_t)trow * K_TOTAL + tkc * 8;
    const __half* bptr = g_wh + (size_t)nt * BN * K_TOTAL + (size_t)trow * K_TOTAL + tkc * 8;
    const uint32_t adst0 = sb + SMEM_STAGE0 + swz128(trow * 128 + tkc * 16);
    const uint32_t bdst0 = adst0 + A_TILE_BYTES;

    int psd = 0;
    auto produce = [&]() {
        uint32_t as = adst0 + psd * STAGE_BYTES;
        uint32_t bs = bdst0 + psd * STAGE_BYTES;
        #pragma unroll
        for (int i = 0; i < 8; i++)
            cp_async16(as + i * 2048, aptr + (size_t)i * 16 * K_TOTAL);
        #pragma unroll
        for (int i = 0; i < 8; i++)
            cp_async16(bs + i * 2048, bptr + (size_t)i * 16 * K_TOTAL);
        cp_async_arrive(sb + SMEM_MBAR + psd * 8);
        aptr += BK;
        bptr += BK;
        if (++psd == STAGES) psd = 0;
    };

    produce();   // kt = 0 -> stage 0
    produce();   // kt = 1 -> stage 1

    // ---- hoisted consumer fragment offsets ----
    const int lrow = (lane & 7) + ((lane >> 3) & 1) * 8;
    const int lhi = lane >> 4;
    uint32_t off_a[4], off_b[4];
    #pragma unroll
    for (int mi = 0; mi < 4; mi++)
        off_a[mi] = swz128((warp_m * 64 + mi * 16 + lrow) * 128 + lhi * 16);
    #pragma unroll
    for (int ni = 0; ni < 4; ni++)
        off_b[ni] = swz128((warp_n * 64 + ni * 16 + lrow) * 128 + lhi * 16);

    float acc[4][8][4];
    #pragma unroll
    for (int i = 0; i < 4; i++)
        #pragma unroll
        for (int j = 0; j < 8; j++)
            #pragma unroll
            for (int c = 0; c < 4; c++) acc[i][j][c] = 0.0f;

    // cross-kk double-buffered fragments
    uint32_t af[2][4][4], bf[2][4][4];

    int cons_s = 0, cons_ph = 0;
    int prod_fw = 0;                             // first free-wait on each stage: parity 0

    for (int kt = 0; kt < NK; kt++) {
        if (kt + 2 < NK) {
            if (kt > 0) {
                mbar_wait(sb + SMEM_MBAR + 24 + psd * 8, prod_fw);
                if (psd == STAGES - 1) prod_fw ^= 1;
            }
            produce();
        }

        mbar_wait(sb + SMEM_MBAR + cons_s * 8, cons_ph);
        uint32_t abase = sb + SMEM_STAGE0 + cons_s * STAGE_BYTES;
        uint32_t bbase = abase + A_TILE_BYTES;

        // lambda: load all 8 fragments of k16-step kk into buffer buf
        auto load_frags = [&](int buf, int kk) {
            uint32_t kx = (uint32_t)(kk * 32);
            #pragma unroll
            for (int ni = 0; ni < 4; ni++)
                ldsm_x4(bf[buf][ni], bbase + (off_b[ni] ^ kx));
            #pragma unroll
            for (int mi = 0; mi < 4; mi++)
                ldsm_x4(af[buf][mi], abase + (off_a[mi] ^ kx));
        };

        load_frags(0, 0);
        #pragma unroll
        for (int kk = 0; kk < 4; kk++) {
            int cur = kk & 1;
            if (kk < 3) load_frags(cur ^ 1, kk + 1);   // hide LDS latency in MMA window
            // after kk==2's prefetch, every ldsm touching this stage has issued
            if (kk == 3 && lane == 0)
                MBAR_ARRIVE(sb + SMEM_MBAR + 24 + cons_s * 8);
            #pragma unroll
            for (int mi = 0; mi < 4; mi++)
                #pragma unroll
                for (int j = 0; j < 8; j++) {
                    int ni = j >> 1, sel = j & 1;
                    mma_16816(acc[mi][j], af[cur][mi], bf[cur][ni][0 + sel], bf[cur][ni][2 + sel]);
                }
        }
        if (++cons_s == STAGES) { cons_s = 0; cons_ph ^= 1; }
    }

    // ---- epilogue: registers -> gmem with quantized bias ----
    const int qrow = lane >> 2, qcol = (lane & 3) * 2;
    #pragma unroll
    for (int mi = 0; mi < 4; mi++) {
        #pragma unroll
        for (int j = 0; j < 8; j++) {
            int n_off = warp_n * 64 + j * 8 + qcol;
            float b0 = qb[n_off], b1 = qb[n_off + 1];
            size_t m0 = (size_t)mt * BM + warp_m * 64 + mi * 16 + qrow;
            float* p0 = out + m0 * N_TOTAL + nt * BN + n_off;
            float* p1 = p0 + 8 * N_TOTAL;
            float2 v0 = {acc[mi][j][0] + b0, acc[mi][j][1] + b1};
            float2 v1 = {acc[mi][j][2] + b0, acc[mi][j][3] + b1};
            *reinterpret_cast<float2*>(p0) = v0;
            *reinterpret_cast<float2*>(p1) = v1;
        }
    }
}

// ---------------------------------------------------------------- launch

extern "C" void kernel_launch(void* const* d_in, const int* in_sizes, int n_in,
                              void* d_out, int out_size) {
    const float* x = (const float*)d_in[0];       // [8, 2048, 4096]
    const float* w = (const float*)d_in[1];       // [4096, 4096]
    const float* b = (const float*)d_in[2];       // [4096]
    float* out = (float*)d_out;

    cudaFuncSetAttribute(bitlinear_gemm,
                         cudaFuncAttributeMaxDynamicSharedMemorySize, SMEM_TOTAL);

    convert_x_kernel<<<32768, 256>>>(x);          // 64M halfs / 8 per thread
    convert_w_kernel<<<8192, 256>>>(w);           // 16M halfs / 8 per thread
    align_nop_kernel<<<1, 32>>>();                // shift ncu -s 5 onto the GEMM
    bitlinear_gemm<<<dim3(N_TOTAL / BN, M_TOTAL / BM), THREADS, SMEM_TOTAL>>>(b, out);
}